// round 14
// baseline (speedup 1.0000x reference)
#include <cuda_runtime.h>
#include <cuda_bf16.h>
#include <math.h>
#include <stdint.h>

// ---------------------------------------------------------------------------
// Problem constants
// ---------------------------------------------------------------------------
#define T_SEQ 2048
#define HID   3584
#define NH    16
#define NKV   8
#define HD    256
#define QKV_COLS ((NH + 2 * NKV) * HD)   // 8192
#define K_OFF (NH * HD)                  // 4096
#define V_OFF ((NH + NKV) * HD)          // 6144
#define ATTN_COLS (NH * HD)              // 4096

#define SOFT_CAP 50.0f
#define ATTN_SCALE 0.0625f               // 256^-0.5
#define NEG_INF __int_as_float(0xff800000)

// ---------------------------------------------------------------------------
// Static device scratch
// ---------------------------------------------------------------------------
__device__ float g_qkv[(size_t)T_SEQ * QKV_COLS];              // fp32 qkv

__device__ __nv_bfloat16 g_hc_h[(size_t)T_SEQ * HID];
__device__ __nv_bfloat16 g_hc_l[(size_t)T_SEQ * HID];
__device__ __nv_bfloat16 g_wqkvT_h[(size_t)QKV_COLS * HID];
__device__ __nv_bfloat16 g_wqkvT_l[(size_t)QKV_COLS * HID];
__device__ __nv_bfloat16 g_woT_h[(size_t)HID * ATTN_COLS];
__device__ __nv_bfloat16 g_woT_l[(size_t)HID * ATTN_COLS];
__device__ __nv_bfloat16 g_qkvc_h[(size_t)T_SEQ * QKV_COLS];
__device__ __nv_bfloat16 g_qkvc_l[(size_t)T_SEQ * QKV_COLS];
__device__ __nv_bfloat16 g_vTc_h[(size_t)NKV * HD * T_SEQ];
__device__ __nv_bfloat16 g_vTc_l[(size_t)NKV * HD * T_SEQ];
__device__ __nv_bfloat16 g_attnc_h[(size_t)T_SEQ * ATTN_COLS];
__device__ __nv_bfloat16 g_attnc_l[(size_t)T_SEQ * ATTN_COLS];

// ---------------------------------------------------------------------------
// PTX helpers
// ---------------------------------------------------------------------------
__device__ __forceinline__ uint32_t smem_u32(const void* p) {
    uint32_t a;
    asm("{ .reg .u64 t; cvta.to.shared.u64 t, %1; cvt.u32.u64 %0, t; }" : "=r"(a) : "l"(p));
    return a;
}
__device__ __forceinline__ void ldgsts16(uint32_t s, const void* g) {
    asm volatile("cp.async.cg.shared.global [%0], [%1], 16;" :: "r"(s), "l"(g));
}
__device__ __forceinline__ void ldsm4(uint32_t* r, uint32_t a) {
    asm volatile("ldmatrix.sync.aligned.m8n8.x4.shared.b16 {%0,%1,%2,%3}, [%4];"
        : "=r"(r[0]), "=r"(r[1]), "=r"(r[2]), "=r"(r[3]) : "r"(a));
}
__device__ __forceinline__ void sts32(uint32_t a, uint32_t v) {
    asm volatile("st.shared.b32 [%0], %1;" :: "r"(a), "r"(v) : "memory");
}
__device__ __forceinline__ void mma16816(float* d, const uint32_t* a, const uint32_t* b) {
    asm volatile("mma.sync.aligned.m16n8k16.row.col.f32.bf16.bf16.f32 "
        "{%0,%1,%2,%3}, {%4,%5,%6,%7}, {%8,%9}, {%0,%1,%2,%3};"
        : "+f"(d[0]), "+f"(d[1]), "+f"(d[2]), "+f"(d[3])
        : "r"(a[0]), "r"(a[1]), "r"(a[2]), "r"(a[3]), "r"(b[0]), "r"(b[1]));
}
// fast softcap: SOFT_CAP * tanh(x * ATTN_SCALE / SOFT_CAP)
__device__ __forceinline__ float softcap(float x) {
    float y = x * (2.0f * ATTN_SCALE / SOFT_CAP);
    y = fminf(fmaxf(y, -30.0f), 30.0f);
    float t = __expf(y);
    return SOFT_CAP * __fdividef(t - 1.0f, t + 1.0f);
}

// ---------------------------------------------------------------------------
// HMMA GEMM (R3/R11 core, untouched):  C[z] = A[z] @ B[z/bDiv]^T
// ---------------------------------------------------------------------------
#define STAGE_B 65536
#define GEMM_SMEM (2 * STAGE_B + 1024)

template<int EPI, int CAUSAL>
__global__ void __launch_bounds__(256, 1)
gemm_mma(const __nv_bfloat16* __restrict__ Ah, const __nv_bfloat16* __restrict__ Al,
         const __nv_bfloat16* __restrict__ Bh, const __nv_bfloat16* __restrict__ Bl,
         float* __restrict__ C, __nv_bfloat16* __restrict__ Ch, __nv_bfloat16* __restrict__ Cl,
         int K, int lda, int ldb, int ldc,
         long long sA, long long sB, long long sC, int bDiv)
{
    extern __shared__ char dsm[];
    const int tid = threadIdx.x;
    const int wid = tid >> 5;
    const int lane = tid & 31;
    const int row0 = blockIdx.y * 128;
    const int col0 = blockIdx.x * 128;

    if (CAUSAL == 1 && col0 >= row0 + 128) return;

    const long long z = blockIdx.z;
    Ah += z * sA;  Al += z * sA;
    Bh += (z / bDiv) * sB;  Bl += (z / bDiv) * sB;

    const uint32_t raw = smem_u32(dsm);
    const uint32_t sb0 = (raw + 1023) & ~1023u;

    int nCh = K >> 6;
    if (CAUSAL == 2) { int lim = (row0 >> 6) + 2; if (lim < nCh) nCh = lim; }

    float acc[4][4][4];
    #pragma unroll
    for (int a = 0; a < 4; a++)
        #pragma unroll
        for (int b = 0; b < 4; b++)
            #pragma unroll
            for (int c = 0; c < 4; c++) acc[a][b][c] = 0.0f;

    const int m0w = (wid & 1) * 64;
    const int n0w = (wid >> 1) * 32;
    const int aRowL = lane & 15;
    const int aColL = (lane >> 4) << 3;
    const int bRowL = (lane & 7) + ((lane >> 4) << 3);
    const int bColL = ((lane >> 3) & 1) << 3;

    auto issue = [&](int ic) {
        const int k0 = ic << 6;
        const uint32_t st = sb0 + (ic & 1) * STAGE_B;
        #pragma unroll
        for (int i = 0; i < 4; i++) {
            int t = tid + i * 256;
            int r = t >> 3, chn = t & 7;
            uint32_t off = (uint32_t)(r * 128 + chn * 16);
            off ^= (off >> 3) & 0x70;
            long long ga = (long long)(row0 + r) * lda + k0 + chn * 8;
            long long gb = (long long)(col0 + r) * ldb + k0 + chn * 8;
            ldgsts16(st + off,         Ah + ga);
            ldgsts16(st + 16384 + off, Al + ga);
            ldgsts16(st + 32768 + off, Bh + gb);
            ldgsts16(st + 49152 + off, Bl + gb);
        }
    };

    issue(0);
    asm volatile("cp.async.commit_group;" ::: "memory");

    for (int ic = 0; ic < nCh; ic++) {
        if (ic + 1 < nCh) issue(ic + 1);
        asm volatile("cp.async.commit_group;" ::: "memory");
        asm volatile("cp.async.wait_group 1;" ::: "memory");
        __syncthreads();

        const uint32_t st = sb0 + (ic & 1) * STAGE_B;
        #pragma unroll
        for (int ks = 0; ks < 4; ks++) {
            const int k0e = ks * 16;
            uint32_t ah[4][4], al[4][4], bh[2][4], bl[2][4];
            #pragma unroll
            for (int mt = 0; mt < 4; mt++) {
                uint32_t off = (uint32_t)((m0w + mt * 16 + aRowL) * 128 + (k0e + aColL) * 2);
                off ^= (off >> 3) & 0x70;
                ldsm4(ah[mt], st + off);
            }
            #pragma unroll
            for (int p = 0; p < 2; p++) {
                uint32_t off = (uint32_t)((n0w + p * 16 + bRowL) * 128 + (k0e + bColL) * 2);
                off ^= (off >> 3) & 0x70;
                ldsm4(bh[p], st + 32768 + off);
            }
            #pragma unroll
            for (int mt = 0; mt < 4; mt++)
                #pragma unroll
                for (int nt = 0; nt < 4; nt++)
                    mma16816(acc[mt][nt], ah[mt], &bh[nt >> 1][(nt & 1) * 2]);
            #pragma unroll
            for (int p = 0; p < 2; p++) {
                uint32_t off = (uint32_t)((n0w + p * 16 + bRowL) * 128 + (k0e + bColL) * 2);
                off ^= (off >> 3) & 0x70;
                ldsm4(bl[p], st + 49152 + off);
            }
            #pragma unroll
            for (int mt = 0; mt < 4; mt++)
                #pragma unroll
                for (int nt = 0; nt < 4; nt++)
                    mma16816(acc[mt][nt], ah[mt], &bl[nt >> 1][(nt & 1) * 2]);
            #pragma unroll
            for (int mt = 0; mt < 4; mt++) {
                uint32_t off = (uint32_t)((m0w + mt * 16 + aRowL) * 128 + (k0e + aColL) * 2);
                off ^= (off >> 3) & 0x70;
                ldsm4(al[mt], st + 16384 + off);
            }
            #pragma unroll
            for (int mt = 0; mt < 4; mt++)
                #pragma unroll
                for (int nt = 0; nt < 4; nt++)
                    mma16816(acc[mt][nt], al[mt], &bh[nt >> 1][(nt & 1) * 2]);
        }
        __syncthreads();
    }

    if (EPI <= 1) C += z * sC;
    else { Ch += z * sC; Cl += z * sC; }

    #pragma unroll
    for (int mt = 0; mt < 4; mt++) {
        #pragma unroll
        for (int nt = 0; nt < 4; nt++) {
            const int r = row0 + m0w + mt * 16 + (lane >> 2);
            const int c = col0 + n0w + nt * 8 + (lane & 3) * 2;
            float d0 = acc[mt][nt][0], d1 = acc[mt][nt][1];
            float d2 = acc[mt][nt][2], d3 = acc[mt][nt][3];
            if (EPI == 1) {
                d0 = softcap(d0); d1 = softcap(d1);
                d2 = softcap(d2); d3 = softcap(d3);
            }
            if (EPI <= 1) {
                *reinterpret_cast<float2*>(C + (long long)r * ldc + c)       = make_float2(d0, d1);
                *reinterpret_cast<float2*>(C + (long long)(r + 8) * ldc + c) = make_float2(d2, d3);
            } else {
                __nv_bfloat16 h0 = __float2bfloat16(d0), h1 = __float2bfloat16(d1);
                __nv_bfloat16 h2 = __float2bfloat16(d2), h3 = __float2bfloat16(d3);
                __nv_bfloat162 hv0(h0, h1), hv1(h2, h3);
                __nv_bfloat162 lv0(__float2bfloat16(d0 - __bfloat162float(h0)),
                                   __float2bfloat16(d1 - __bfloat162float(h1)));
                __nv_bfloat162 lv1(__float2bfloat16(d2 - __bfloat162float(h2)),
                                   __float2bfloat16(d3 - __bfloat162float(h3)));
                *reinterpret_cast<__nv_bfloat162*>(Ch + (long long)r * ldc + c)       = hv0;
                *reinterpret_cast<__nv_bfloat162*>(Cl + (long long)r * ldc + c)       = lv0;
                *reinterpret_cast<__nv_bfloat162*>(Ch + (long long)(r + 8) * ldc + c) = hv1;
                *reinterpret_cast<__nv_bfloat162*>(Cl + (long long)(r + 8) * ldc + c) = lv1;
            }
        }
    }
}

// ---------------------------------------------------------------------------
// Fused flash attention v2 (R13, unchanged): persistent Q + K/V chunk ring.
// ---------------------------------------------------------------------------
#define FL_SLOT  65536
#define FL_PBASE (2 * FL_SLOT)           // 131072
#define FL_QBASE (FL_PBASE + 32768)      // 163840
#define FL_SMEM  (FL_QBASE + 65536 + 128)

__global__ void __launch_bounds__(256, 1)
flash_attn(const __nv_bfloat16* __restrict__ qh, const __nv_bfloat16* __restrict__ ql,
           const __nv_bfloat16* __restrict__ vh, const __nv_bfloat16* __restrict__ vl,
           __nv_bfloat16* __restrict__ ohh, __nv_bfloat16* __restrict__ oll)
{
    extern __shared__ char dsm[];
    __shared__ float redm[64][4];
    __shared__ float redl[64][4];

    const int tid  = threadIdx.x;
    const int wid  = tid >> 5;
    const int lane = tid & 31;
    const int wm = wid >> 2;
    const int wn = wid & 3;
    const int b  = 31 - blockIdx.x;      // heavy q-blocks first
    const int h  = blockIdx.y;
    const int kvh = h >> 1;
    const int qcol = h * HD;
    const int kcol = K_OFF + kvh * HD;
    const int vrow = kvh * HD;
    const int row0 = b * 64;
    const int jmax = b >> 1;

    const uint32_t raw = smem_u32(dsm);
    const uint32_t sb0 = (raw + 127) & ~127u;
    const uint32_t pB  = sb0 + FL_PBASE;
    const uint32_t qB  = sb0 + FL_QBASE;

    const int aRowL = lane & 15;
    const int aColL = (lane >> 4) << 3;
    const int bRowL = (lane & 7) + ((lane >> 4) << 3);
    const int bColL = ((lane >> 3) & 1) << 3;

    float o[2][8][4];
    #pragma unroll
    for (int mt = 0; mt < 2; mt++)
        #pragma unroll
        for (int nt = 0; nt < 8; nt++)
            #pragma unroll
            for (int e = 0; e < 4; e++) o[mt][nt][e] = 0.0f;
    float mrow[4] = {NEG_INF, NEG_INF, NEG_INF, NEG_INF};
    float lrow[4] = {0.0f, 0.0f, 0.0f, 0.0f};

    // ---- persistent Q load ----
    #pragma unroll
    for (int i = 0; i < 8; i++) {
        int idx = tid + i * 256;
        int r = idx >> 5, ch = idx & 31;
        int dblk = ch >> 3, c8 = ch & 7;
        uint32_t off = (uint32_t)(r * 128 + c8 * 16);
        off ^= (off >> 3) & 0x70;
        long long g = (long long)(row0 + r) * QKV_COLS + qcol + ch * 8;
        ldgsts16(qB + dblk * 8192 + off,         qh + g);
        ldgsts16(qB + 32768 + dblk * 8192 + off, ql + g);
    }
    asm volatile("cp.async.commit_group;" ::: "memory");

    auto issueK = [&](int j, int kc, int sl) {
        const uint32_t st = sb0 + sl * FL_SLOT;
        const int krow0 = j * 128;
        #pragma unroll
        for (int i = 0; i < 8; i++) {
            int idx = tid + i * 256;
            int r = idx >> 4, ch = idx & 15;
            int sub = ch >> 3, c8 = ch & 7;
            uint32_t off = (uint32_t)(r * 128 + c8 * 16);
            off ^= (off >> 3) & 0x70;
            long long g = (long long)(krow0 + r) * QKV_COLS + kcol + kc * 128 + ch * 8;
            ldgsts16(st + sub * 16384 + off,         qh + g);
            ldgsts16(st + 32768 + sub * 16384 + off, ql + g);
        }
    };
    auto issueV = [&](int j, int tc, int sl) {
        const uint32_t st = sb0 + sl * FL_SLOT;
        const int t0 = j * 128 + tc * 64;
        #pragma unroll
        for (int i = 0; i < 8; i++) {
            int idx = tid + i * 256;
            int r = idx >> 3, ch = idx & 7;
            uint32_t off = (uint32_t)(r * 128 + ch * 16);
            off ^= (off >> 3) & 0x70;
            long long g = (long long)(vrow + r) * T_SEQ + t0 + ch * 8;
            ldgsts16(st + off,         vh + g);
            ldgsts16(st + 32768 + off, vl + g);
        }
    };
    auto issueChunk = [&](int j, int c, int sl) {
        if (c < 2) issueK(j, c, sl); else issueV(j, c - 2, sl);
    };

    issueChunk(0, 0, 0);
    asm volatile("cp.async.commit_group;" ::: "memory");

    float sacc[2][4][4];
    int step = 0;
    #pragma unroll 1
    for (int j = 0; j <= jmax; j++) {
        #pragma unroll
        for (int mt = 0; mt < 2; mt++)
            #pragma unroll
            for (int nt = 0; nt < 4; nt++)
                #pragma unroll
                for (int e = 0; e < 4; e++) sacc[mt][nt][e] = 0.0f;

        #pragma unroll 1
        for (int c = 0; c < 4; c++) {
            int nj = j, nc = c + 1;
            if (nc == 4) { nj = j + 1; nc = 0; }
            if (nj <= jmax) issueChunk(nj, nc, (step + 1) & 1);
            asm volatile("cp.async.commit_group;" ::: "memory");
            asm volatile("cp.async.wait_group 1;" ::: "memory");
            __syncthreads();
            const uint32_t st = sb0 + (step & 1) * FL_SLOT;

            if (c < 2) {
                #pragma unroll
                for (int sub = 0; sub < 2; sub++) {
                    const uint32_t qHi = qB + (c * 2 + sub) * 8192;
                    const uint32_t qLo = qHi + 32768;
                    const uint32_t kHi = st + sub * 16384;
                    const uint32_t kLo = kHi + 32768;
                    #pragma unroll
                    for (int ks = 0; ks < 4; ks++) {
                        const int k0e = ks * 16;
                        uint32_t ah[2][4], al[2][4], bh[2][4], bl[2][4];
                        #pragma unroll
                        for (int mt = 0; mt < 2; mt++) {
                            uint32_t off = (uint32_t)((wm * 32 + mt * 16 + aRowL) * 128 + (k0e + aColL) * 2);
                            off ^= (off >> 3) & 0x70;
                            ldsm4(ah[mt], qHi + off);
                        }
                        #pragma unroll
                        for (int p = 0; p < 2; p++) {
                            uint32_t off = (uint32_t)((wn * 32 + p * 16 + bRowL) * 128 + (k0e + bColL) * 2);
                            off ^= (off >> 3) & 0x70;
                            ldsm4(bh[p], kHi + off);
                        }
                        #pragma unroll
                        for (int mt = 0; mt < 2; mt++)
                            #pragma unroll
                            for (int nt = 0; nt < 4; nt++)
                                mma16816(sacc[mt][nt], ah[mt], &bh[nt >> 1][(nt & 1) * 2]);
                        #pragma unroll
                        for (int p = 0; p < 2; p++) {
                            uint32_t off = (uint32_t)((wn * 32 + p * 16 + bRowL) * 128 + (k0e + bColL) * 2);
                            off ^= (off >> 3) & 0x70;
                            ldsm4(bl[p], kLo + off);
                        }
                        #pragma unroll
                        for (int mt = 0; mt < 2; mt++)
                            #pragma unroll
                            for (int nt = 0; nt < 4; nt++)
                                mma16816(sacc[mt][nt], ah[mt], &bl[nt >> 1][(nt & 1) * 2]);
                        #pragma unroll
                        for (int mt = 0; mt < 2; mt++) {
                            uint32_t off = (uint32_t)((wm * 32 + mt * 16 + aRowL) * 128 + (k0e + aColL) * 2);
                            off ^= (off >> 3) & 0x70;
                            ldsm4(al[mt], qLo + off);
                        }
                        #pragma unroll
                        for (int mt = 0; mt < 2; mt++)
                            #pragma unroll
                            for (int nt = 0; nt < 4; nt++)
                                mma16816(sacc[mt][nt], al[mt], &bh[nt >> 1][(nt & 1) * 2]);
                    }
                }

                if (c == 1) {
                    const bool diag = (j == jmax);
                    #pragma unroll
                    for (int mt = 0; mt < 2; mt++)
                        #pragma unroll
                        for (int nt = 0; nt < 4; nt++)
                            #pragma unroll
                            for (int e = 0; e < 4; e++) {
                                float x = softcap(sacc[mt][nt][e]);
                                if (diag) {
                                    int rg = row0 + wm * 32 + mt * 16 + (lane >> 2) + ((e >> 1) << 3);
                                    int cg = j * 128 + wn * 32 + nt * 8 + ((lane & 3) << 1) + (e & 1);
                                    if (cg > rg) x = NEG_INF;
                                }
                                sacc[mt][nt][e] = x;
                            }
                    float alpha[4];
                    #pragma unroll
                    for (int mt = 0; mt < 2; mt++)
                        #pragma unroll
                        for (int hb = 0; hb < 2; hb++) {
                            float mm = NEG_INF;
                            #pragma unroll
                            for (int nt = 0; nt < 4; nt++)
                                mm = fmaxf(mm, fmaxf(sacc[mt][nt][2 * hb], sacc[mt][nt][2 * hb + 1]));
                            mm = fmaxf(mm, __shfl_xor_sync(0xffffffffu, mm, 1));
                            mm = fmaxf(mm, __shfl_xor_sync(0xffffffffu, mm, 2));
                            if ((lane & 3) == 0)
                                redm[wm * 32 + mt * 16 + (lane >> 2) + hb * 8][wn] = mm;
                        }
                    __syncthreads();
                    #pragma unroll
                    for (int mt = 0; mt < 2; mt++)
                        #pragma unroll
                        for (int hb = 0; hb < 2; hb++) {
                            int r = wm * 32 + mt * 16 + (lane >> 2) + hb * 8;
                            int s = mt * 2 + hb;
                            float bm = fmaxf(fmaxf(redm[r][0], redm[r][1]),
                                             fmaxf(redm[r][2], redm[r][3]));
                            float mn = fmaxf(mrow[s], bm);
                            alpha[s] = __expf(mrow[s] - mn);
                            mrow[s] = mn;
                        }
                    float ps[4] = {0.0f, 0.0f, 0.0f, 0.0f};
                    #pragma unroll
                    for (int mt = 0; mt < 2; mt++)
                        #pragma unroll
                        for (int nt = 0; nt < 4; nt++)
                            #pragma unroll
                            for (int e = 0; e < 4; e++) {
                                int s = mt * 2 + (e >> 1);
                                float pe = __expf(sacc[mt][nt][e] - mrow[s]);
                                sacc[mt][nt][e] = pe;
                                ps[s] += pe;
                            }
                    #pragma unroll
                    for (int mt = 0; mt < 2; mt++)
                        #pragma unroll
                        for (int hb = 0; hb < 2; hb++) {
                            int s = mt * 2 + hb;
                            float v = ps[s];
                            v += __shfl_xor_sync(0xffffffffu, v, 1);
                            v += __shfl_xor_sync(0xffffffffu, v, 2);
                            if ((lane & 3) == 0)
                                redl[wm * 32 + mt * 16 + (lane >> 2) + hb * 8][wn] = v;
                        }
                    __syncthreads();
                    #pragma unroll
                    for (int mt = 0; mt < 2; mt++)
                        #pragma unroll
                        for (int hb = 0; hb < 2; hb++) {
                            int r = wm * 32 + mt * 16 + (lane >> 2) + hb * 8;
                            int s = mt * 2 + hb;
                            float bs = (redl[r][0] + redl[r][1]) + (redl[r][2] + redl[r][3]);
                            lrow[s] = lrow[s] * alpha[s] + bs;
                        }
                    #pragma unroll
                    for (int mt = 0; mt < 2; mt++)
                        #pragma unroll
                        for (int nt = 0; nt < 8; nt++)
                            #pragma unroll
                            for (int e = 0; e < 4; e++)
                                o[mt][nt][e] *= alpha[mt * 2 + (e >> 1)];
                    #pragma unroll
                    for (int mt = 0; mt < 2; mt++)
                        #pragma unroll
                        for (int nt = 0; nt < 4; nt++)
                            #pragma unroll
                            for (int hb = 0; hb < 2; hb++) {
                                int r = wm * 32 + mt * 16 + (lane >> 2) + hb * 8;
                                int col = wn * 32 + nt * 8 + ((lane & 3) << 1);
                                uint32_t hbase = pB + ((col >> 6) ? 8192u : 0u);
                                uint32_t off = (uint32_t)(r * 128 + (col & 63) * 2);
                                off ^= (off >> 3) & 0x70;
                                float p0 = sacc[mt][nt][2 * hb], p1 = sacc[mt][nt][2 * hb + 1];
                                __nv_bfloat16 h0 = __float2bfloat16(p0), h1 = __float2bfloat16(p1);
                                __nv_bfloat162 hv(h0, h1);
                                __nv_bfloat162 lv(__float2bfloat16(p0 - __bfloat162float(h0)),
                                                  __float2bfloat16(p1 - __bfloat162float(h1)));
                                sts32(hbase + off,         *reinterpret_cast<uint32_t*>(&hv));
                                sts32(hbase + 16384 + off, *reinterpret_cast<uint32_t*>(&lv));
                            }
                }
            } else {
                const int tc = c - 2;
                const uint32_t PhA = pB + tc * 8192;
                const uint32_t PlA = PhA + 16384;
                #pragma unroll
                for (int ks = 0; ks < 4; ks++) {
                    const int k0e = ks * 16;
                    uint32_t ap[2][4], apl[2][4], bvh[4][4], bvl[4][4];
                    #pragma unroll
                    for (int mt = 0; mt < 2; mt++) {
                        uint32_t off = (uint32_t)((wm * 32 + mt * 16 + aRowL) * 128 + (k0e + aColL) * 2);
                        off ^= (off >> 3) & 0x70;
                        ldsm4(ap[mt], PhA + off);
                    }
                    #pragma unroll
                    for (int p = 0; p < 4; p++) {
                        uint32_t off = (uint32_t)((wn * 64 + p * 16 + bRowL) * 128 + (k0e + bColL) * 2);
                        off ^= (off >> 3) & 0x70;
                        ldsm4(bvh[p], st + off);
                    }
                    #pragma unroll
                    for (int mt = 0; mt < 2; mt++)
                        #pragma unroll
                        for (int nt = 0; nt < 8; nt++)
                            mma16816(o[mt][nt], ap[mt], &bvh[nt >> 1][(nt & 1) * 2]);
                    #pragma unroll
                    for (int p = 0; p < 4; p++) {
                        uint32_t off = (uint32_t)((wn * 64 + p * 16 + bRowL) * 128 + (k0e + bColL) * 2);
                        off ^= (off >> 3) & 0x70;
                        ldsm4(bvl[p], st + 32768 + off);
                    }
                    #pragma unroll
                    for (int mt = 0; mt < 2; mt++)
                        #pragma unroll
                        for (int nt = 0; nt < 8; nt++)
                            mma16816(o[mt][nt], ap[mt], &bvl[nt >> 1][(nt & 1) * 2]);
                    #pragma unroll
                    for (int mt = 0; mt < 2; mt++) {
                        uint32_t off = (uint32_t)((wm * 32 + mt * 16 + aRowL) * 128 + (k0e + aColL) * 2);
                        off ^= (off >> 3) & 0x70;
                        ldsm4(apl[mt], PlA + off);
                    }
                    #pragma unroll
                    for (int mt = 0; mt < 2; mt++)
                        #pragma unroll
                        for (int nt = 0; nt < 8; nt++)
                            mma16816(o[mt][nt], apl[mt], &bvh[nt >> 1][(nt & 1) * 2]);
                }
            }
            __syncthreads();
            step++;
        }
    }

    float invl[4];
    #pragma unroll
    for (int s = 0; s < 4; s++) invl[s] = 1.0f / lrow[s];

    #pragma unroll
    for (int mt = 0; mt < 2; mt++) {
        #pragma unroll
        for (int nt = 0; nt < 8; nt++) {
            const int r = row0 + wm * 32 + mt * 16 + (lane >> 2);
            const int col = qcol + wn * 64 + nt * 8 + ((lane & 3) << 1);
            float d0 = o[mt][nt][0] * invl[mt * 2];
            float d1 = o[mt][nt][1] * invl[mt * 2];
            float d2 = o[mt][nt][2] * invl[mt * 2 + 1];
            float d3 = o[mt][nt][3] * invl[mt * 2 + 1];
            __nv_bfloat16 h0 = __float2bfloat16(d0), h1 = __float2bfloat16(d1);
            __nv_bfloat16 h2 = __float2bfloat16(d2), h3 = __float2bfloat16(d3);
            __nv_bfloat162 hv0(h0, h1), hv1(h2, h3);
            __nv_bfloat162 lv0(__float2bfloat16(d0 - __bfloat162float(h0)),
                               __float2bfloat16(d1 - __bfloat162float(h1)));
            __nv_bfloat162 lv1(__float2bfloat16(d2 - __bfloat162float(h2)),
                               __float2bfloat16(d3 - __bfloat162float(h3)));
            *reinterpret_cast<__nv_bfloat162*>(ohh + (long long)r * ATTN_COLS + col)       = hv0;
            *reinterpret_cast<__nv_bfloat162*>(oll + (long long)r * ATTN_COLS + col)       = lv0;
            *reinterpret_cast<__nv_bfloat162*>(ohh + (long long)(r + 8) * ATTN_COLS + col) = hv1;
            *reinterpret_cast<__nv_bfloat162*>(oll + (long long)(r + 8) * ATTN_COLS + col) = lv1;
        }
    }
}

// ---------------------------------------------------------------------------
// fp32 -> (hi, lo) bf16 split, elementwise
// ---------------------------------------------------------------------------
__global__ void __launch_bounds__(256)
convsplit(const float4* __restrict__ x, __nv_bfloat162* __restrict__ hi,
          __nv_bfloat162* __restrict__ lo, long long n4)
{
    long long i = (long long)blockIdx.x * 256 + threadIdx.x;
    if (i >= n4) return;
    float4 v = x[i];
    __nv_bfloat16 h0 = __float2bfloat16(v.x), h1 = __float2bfloat16(v.y);
    __nv_bfloat16 h2 = __float2bfloat16(v.z), h3 = __float2bfloat16(v.w);
    hi[2 * i]     = __nv_bfloat162(h0, h1);
    hi[2 * i + 1] = __nv_bfloat162(h2, h3);
    lo[2 * i]     = __nv_bfloat162(__float2bfloat16(v.x - __bfloat162float(h0)),
                                   __float2bfloat16(v.y - __bfloat162float(h1)));
    lo[2 * i + 1] = __nv_bfloat162(__float2bfloat16(v.z - __bfloat162float(h2)),
                                   __float2bfloat16(v.w - __bfloat162float(h3)));
}

// ---------------------------------------------------------------------------
// Transpose + split: in[R,C] fp32 (ldin) -> out[C,R] (hi, lo) bf16 (ldout)
// ---------------------------------------------------------------------------
__global__ void __launch_bounds__(256)
tsplit(const float* __restrict__ in, int ldin, __nv_bfloat16* __restrict__ oh,
       __nv_bfloat16* __restrict__ ol, int ldout)
{
    __shared__ float t[32][33];
    int bx = blockIdx.x * 32, by = blockIdx.y * 32;
    int tx = threadIdx.x, ty = threadIdx.y;
    #pragma unroll
    for (int j = ty; j < 32; j += 8)
        t[j][tx] = in[(long long)(by + j) * ldin + bx + tx];
    __syncthreads();
    #pragma unroll
    for (int j = ty; j < 32; j += 8) {
        float v = t[tx][j];
        __nv_bfloat16 h = __float2bfloat16(v);
        long long o = (long long)(bx + j) * ldout + by + tx;
        oh[o] = h;
        ol[o] = __float2bfloat16(v - __bfloat162float(h));
    }
}

// ---------------------------------------------------------------------------
// Fused RoPE + split: reads fp32 qkv (Q,K region), writes split bf16 pair
// ---------------------------------------------------------------------------
__global__ void __launch_bounds__(256)
rope_split(const float* __restrict__ qkv, const int* __restrict__ positions,
           __nv_bfloat16* __restrict__ oh, __nv_bfloat16* __restrict__ ol)
{
    int idx = blockIdx.x * blockDim.x + threadIdx.x;
    int i = idx & 127;
    int h = (idx >> 7) % (NH + NKV);
    int t = idx / (128 * (NH + NKV));
    if (t >= T_SEQ) return;
    float pos = (float)positions[t];
    float inv = powf(10000.0f, -((2.0f * (float)i) / (float)HD));
    float f = pos * inv;
    float c, s;
    sincosf(f, &s, &c);
    long long base = (long long)t * QKV_COLS + h * HD;
    float x1 = qkv[base + i], x2 = qkv[base + i + HD / 2];
    float y1 = x1 * c - x2 * s;
    float y2 = x2 * c + x1 * s;
    __nv_bfloat16 h1 = __float2bfloat16(y1);
    __nv_bfloat16 h2 = __float2bfloat16(y2);
    oh[base + i]          = h1;
    ol[base + i]          = __float2bfloat16(y1 - __bfloat162float(h1));
    oh[base + i + HD / 2] = h2;
    ol[base + i + HD / 2] = __float2bfloat16(y2 - __bfloat162float(h2));
}

// ---------------------------------------------------------------------------
// kernel_launch — graph-capturable, allocation-free.
// w_o transpose forked onto a side stream so it overlaps the QKV GEMM;
// joined via event before the O-projection.
// ---------------------------------------------------------------------------
extern "C" void kernel_launch(void* const* d_in, const int* in_sizes, int n_in,
                              void* d_out, int out_size)
{
    const int*   positions = (const int*)  d_in[0];
    const float* hidden    = (const float*)d_in[1];
    const float* w_qkv     = (const float*)d_in[2];
    const float* w_o       = (const float*)d_in[3];
    float*       out       = (float*)d_out;

    float *qkv;
    __nv_bfloat16 *hch, *hcl, *wqh, *wql, *woh, *wol, *qch, *qcl, *vch, *vcl, *ach, *acl;
    cudaGetSymbolAddress((void**)&qkv, g_qkv);
    cudaGetSymbolAddress((void**)&hch, g_hc_h);    cudaGetSymbolAddress((void**)&hcl, g_hc_l);
    cudaGetSymbolAddress((void**)&wqh, g_wqkvT_h); cudaGetSymbolAddress((void**)&wql, g_wqkvT_l);
    cudaGetSymbolAddress((void**)&woh, g_woT_h);   cudaGetSymbolAddress((void**)&wol, g_woT_l);
    cudaGetSymbolAddress((void**)&qch, g_qkvc_h);  cudaGetSymbolAddress((void**)&qcl, g_qkvc_l);
    cudaGetSymbolAddress((void**)&vch, g_vTc_h);   cudaGetSymbolAddress((void**)&vcl, g_vTc_l);
    cudaGetSymbolAddress((void**)&ach, g_attnc_h); cudaGetSymbolAddress((void**)&acl, g_attnc_l);

    cudaFuncSetAttribute(gemm_mma<0, 0>, cudaFuncAttributeMaxDynamicSharedMemorySize, GEMM_SMEM);
    cudaFuncSetAttribute(flash_attn, cudaFuncAttributeMaxDynamicSharedMemorySize, FL_SMEM);

    // Side stream + events for the w_o prep fork (host-side objects only;
    // intentionally not destroyed while capture may still be active).
    cudaStream_t s1;
    cudaStreamCreateWithFlags(&s1, cudaStreamNonBlocking);
    cudaEvent_t eFork, eJoin;
    cudaEventCreateWithFlags(&eFork, cudaEventDisableTiming);
    cudaEventCreateWithFlags(&eJoin, cudaEventDisableTiming);

    // Fork: w_o transpose runs concurrently with the main chain (needed only by O-proj)
    cudaEventRecord(eFork, 0);
    cudaStreamWaitEvent(s1, eFork, 0);
    tsplit<<<dim3(HID / 32, ATTN_COLS / 32), dim3(32, 8), 0, s1>>>(w_o, HID, woh, wol, ATTN_COLS);
    cudaEventRecord(eJoin, s1);

    // Main chain (stream 0)
    tsplit<<<dim3(QKV_COLS / 32, HID / 32), dim3(32, 8)>>>(w_qkv, QKV_COLS, wqh, wql, HID);
    {
        long long n4 = (long long)T_SEQ * HID / 4;
        convsplit<<<(unsigned)((n4 + 255) / 256), 256>>>((const float4*)hidden,
            (__nv_bfloat162*)hch, (__nv_bfloat162*)hcl, n4);
    }

    // 1) QKV projection -> fp32 qkv
    gemm_mma<0, 0><<<dim3(QKV_COLS / 128, T_SEQ / 128, 1), 256, GEMM_SMEM>>>(
        hch, hcl, wqh, wql, qkv, nullptr, nullptr,
        HID, HID, HID, QKV_COLS, 0, 0, 0, 1);

    // 2) fused RoPE + split on Q,K;  transpose+split V -> vT
    rope_split<<<(T_SEQ * (NH + NKV) * (HD / 2)) / 256, 256>>>(qkv, positions, qch, qcl);
    tsplit<<<dim3((NKV * HD) / 32, T_SEQ / 32), dim3(32, 8)>>>(qkv + V_OFF, QKV_COLS, vch, vcl, T_SEQ);

    // 3) fused flash attention -> split attn output
    flash_attn<<<dim3(32, NH), 256, FL_SMEM>>>(qch, qcl, vch, vcl, ach, acl);

    // Join: w_o prep must be complete before the output projection
    cudaStreamWaitEvent(0, eJoin, 0);

    // 4) output projection
    gemm_mma<0, 0><<<dim3(HID / 128, T_SEQ / 128, 1), 256, GEMM_SMEM>>>(
        ach, acl, woh, wol, out, nullptr, nullptr,
        ATTN_COLS, ATTN_COLS, ATTN_COLS, HID, 0, 0, 0, 1);
}

// round 17
// speedup vs baseline: 1.0396x; 1.0396x over previous
#include <cuda_runtime.h>
#include <cuda_bf16.h>
#include <math.h>
#include <stdint.h>

// ---------------------------------------------------------------------------
// Problem constants
// ---------------------------------------------------------------------------
#define T_SEQ 2048
#define HID   3584
#define NH    16
#define NKV   8
#define HD    256
#define QKV_COLS ((NH + 2 * NKV) * HD)   // 8192
#define K_OFF (NH * HD)                  // 4096
#define V_OFF ((NH + NKV) * HD)          // 6144
#define ATTN_COLS (NH * HD)              // 4096

#define SOFT_CAP 50.0f
#define ATTN_SCALE 0.0625f               // 256^-0.5
#define NEG_INF __int_as_float(0xff800000)

// ---------------------------------------------------------------------------
// Static device scratch
// ---------------------------------------------------------------------------
__device__ float g_qkv[(size_t)T_SEQ * QKV_COLS];              // fp32 qkv

__device__ __nv_bfloat16 g_hc_h[(size_t)T_SEQ * HID];
__device__ __nv_bfloat16 g_hc_l[(size_t)T_SEQ * HID];
__device__ __nv_bfloat16 g_wqkvT_h[(size_t)QKV_COLS * HID];
__device__ __nv_bfloat16 g_wqkvT_l[(size_t)QKV_COLS * HID];
__device__ __nv_bfloat16 g_woT_h[(size_t)HID * ATTN_COLS];
__device__ __nv_bfloat16 g_woT_l[(size_t)HID * ATTN_COLS];
__device__ __nv_bfloat16 g_qkvc_h[(size_t)T_SEQ * QKV_COLS];
__device__ __nv_bfloat16 g_qkvc_l[(size_t)T_SEQ * QKV_COLS];
__device__ __nv_bfloat16 g_vTc_h[(size_t)NKV * HD * T_SEQ];
__device__ __nv_bfloat16 g_vTc_l[(size_t)NKV * HD * T_SEQ];
__device__ __nv_bfloat16 g_attnc_h[(size_t)T_SEQ * ATTN_COLS];
__device__ __nv_bfloat16 g_attnc_l[(size_t)T_SEQ * ATTN_COLS];

// ---------------------------------------------------------------------------
// PTX helpers
// ---------------------------------------------------------------------------
__device__ __forceinline__ uint32_t smem_u32(const void* p) {
    uint32_t a;
    asm("{ .reg .u64 t; cvta.to.shared.u64 t, %1; cvt.u32.u64 %0, t; }" : "=r"(a) : "l"(p));
    return a;
}
__device__ __forceinline__ void ldgsts16(uint32_t s, const void* g) {
    asm volatile("cp.async.cg.shared.global [%0], [%1], 16;" :: "r"(s), "l"(g));
}
__device__ __forceinline__ void ldsm4(uint32_t* r, uint32_t a) {
    asm volatile("ldmatrix.sync.aligned.m8n8.x4.shared.b16 {%0,%1,%2,%3}, [%4];"
        : "=r"(r[0]), "=r"(r[1]), "=r"(r[2]), "=r"(r[3]) : "r"(a));
}
__device__ __forceinline__ void sts32(uint32_t a, uint32_t v) {
    asm volatile("st.shared.b32 [%0], %1;" :: "r"(a), "r"(v) : "memory");
}
__device__ __forceinline__ void mma16816(float* d, const uint32_t* a, const uint32_t* b) {
    asm volatile("mma.sync.aligned.m16n8k16.row.col.f32.bf16.bf16.f32 "
        "{%0,%1,%2,%3}, {%4,%5,%6,%7}, {%8,%9}, {%0,%1,%2,%3};"
        : "+f"(d[0]), "+f"(d[1]), "+f"(d[2]), "+f"(d[3])
        : "r"(a[0]), "r"(a[1]), "r"(a[2]), "r"(a[3]), "r"(b[0]), "r"(b[1]));
}
// fast softcap: SOFT_CAP * tanh(x * ATTN_SCALE / SOFT_CAP)
__device__ __forceinline__ float softcap(float x) {
    float y = x * (2.0f * ATTN_SCALE / SOFT_CAP);
    y = fminf(fmaxf(y, -30.0f), 30.0f);
    float t = __expf(y);
    return SOFT_CAP * __fdividef(t - 1.0f, t + 1.0f);
}

// ---------------------------------------------------------------------------
// HMMA GEMM (R3/R11 core, untouched):  C[z] = A[z] @ B[z/bDiv]^T
// ---------------------------------------------------------------------------
#define STAGE_B 65536
#define GEMM_SMEM (2 * STAGE_B + 1024)

template<int EPI, int CAUSAL>
__global__ void __launch_bounds__(256, 1)
gemm_mma(const __nv_bfloat16* __restrict__ Ah, const __nv_bfloat16* __restrict__ Al,
         const __nv_bfloat16* __restrict__ Bh, const __nv_bfloat16* __restrict__ Bl,
         float* __restrict__ C, __nv_bfloat16* __restrict__ Ch, __nv_bfloat16* __restrict__ Cl,
         int K, int lda, int ldb, int ldc,
         long long sA, long long sB, long long sC, int bDiv)
{
    extern __shared__ char dsm[];
    const int tid = threadIdx.x;
    const int wid = tid >> 5;
    const int lane = tid & 31;
    const int row0 = blockIdx.y * 128;
    const int col0 = blockIdx.x * 128;

    if (CAUSAL == 1 && col0 >= row0 + 128) return;

    const long long z = blockIdx.z;
    Ah += z * sA;  Al += z * sA;
    Bh += (z / bDiv) * sB;  Bl += (z / bDiv) * sB;

    const uint32_t raw = smem_u32(dsm);
    const uint32_t sb0 = (raw + 1023) & ~1023u;

    int nCh = K >> 6;
    if (CAUSAL == 2) { int lim = (row0 >> 6) + 2; if (lim < nCh) nCh = lim; }

    float acc[4][4][4];
    #pragma unroll
    for (int a = 0; a < 4; a++)
        #pragma unroll
        for (int b = 0; b < 4; b++)
            #pragma unroll
            for (int c = 0; c < 4; c++) acc[a][b][c] = 0.0f;

    const int m0w = (wid & 1) * 64;
    const int n0w = (wid >> 1) * 32;
    const int aRowL = lane & 15;
    const int aColL = (lane >> 4) << 3;
    const int bRowL = (lane & 7) + ((lane >> 4) << 3);
    const int bColL = ((lane >> 3) & 1) << 3;

    auto issue = [&](int ic) {
        const int k0 = ic << 6;
        const uint32_t st = sb0 + (ic & 1) * STAGE_B;
        #pragma unroll
        for (int i = 0; i < 4; i++) {
            int t = tid + i * 256;
            int r = t >> 3, chn = t & 7;
            uint32_t off = (uint32_t)(r * 128 + chn * 16);
            off ^= (off >> 3) & 0x70;
            long long ga = (long long)(row0 + r) * lda + k0 + chn * 8;
            long long gb = (long long)(col0 + r) * ldb + k0 + chn * 8;
            ldgsts16(st + off,         Ah + ga);
            ldgsts16(st + 16384 + off, Al + ga);
            ldgsts16(st + 32768 + off, Bh + gb);
            ldgsts16(st + 49152 + off, Bl + gb);
        }
    };

    issue(0);
    asm volatile("cp.async.commit_group;" ::: "memory");

    for (int ic = 0; ic < nCh; ic++) {
        if (ic + 1 < nCh) issue(ic + 1);
        asm volatile("cp.async.commit_group;" ::: "memory");
        asm volatile("cp.async.wait_group 1;" ::: "memory");
        __syncthreads();

        const uint32_t st = sb0 + (ic & 1) * STAGE_B;
        #pragma unroll
        for (int ks = 0; ks < 4; ks++) {
            const int k0e = ks * 16;
            uint32_t ah[4][4], al[4][4], bh[2][4], bl[2][4];
            #pragma unroll
            for (int mt = 0; mt < 4; mt++) {
                uint32_t off = (uint32_t)((m0w + mt * 16 + aRowL) * 128 + (k0e + aColL) * 2);
                off ^= (off >> 3) & 0x70;
                ldsm4(ah[mt], st + off);
            }
            #pragma unroll
            for (int p = 0; p < 2; p++) {
                uint32_t off = (uint32_t)((n0w + p * 16 + bRowL) * 128 + (k0e + bColL) * 2);
                off ^= (off >> 3) & 0x70;
                ldsm4(bh[p], st + 32768 + off);
            }
            #pragma unroll
            for (int mt = 0; mt < 4; mt++)
                #pragma unroll
                for (int nt = 0; nt < 4; nt++)
                    mma16816(acc[mt][nt], ah[mt], &bh[nt >> 1][(nt & 1) * 2]);
            #pragma unroll
            for (int p = 0; p < 2; p++) {
                uint32_t off = (uint32_t)((n0w + p * 16 + bRowL) * 128 + (k0e + bColL) * 2);
                off ^= (off >> 3) & 0x70;
                ldsm4(bl[p], st + 49152 + off);
            }
            #pragma unroll
            for (int mt = 0; mt < 4; mt++)
                #pragma unroll
                for (int nt = 0; nt < 4; nt++)
                    mma16816(acc[mt][nt], ah[mt], &bl[nt >> 1][(nt & 1) * 2]);
            #pragma unroll
            for (int mt = 0; mt < 4; mt++) {
                uint32_t off = (uint32_t)((m0w + mt * 16 + aRowL) * 128 + (k0e + aColL) * 2);
                off ^= (off >> 3) & 0x70;
                ldsm4(al[mt], st + 16384 + off);
            }
            #pragma unroll
            for (int mt = 0; mt < 4; mt++)
                #pragma unroll
                for (int nt = 0; nt < 4; nt++)
                    mma16816(acc[mt][nt], al[mt], &bh[nt >> 1][(nt & 1) * 2]);
        }
        __syncthreads();
    }

    if (EPI <= 1) C += z * sC;
    else { Ch += z * sC; Cl += z * sC; }

    #pragma unroll
    for (int mt = 0; mt < 4; mt++) {
        #pragma unroll
        for (int nt = 0; nt < 4; nt++) {
            const int r = row0 + m0w + mt * 16 + (lane >> 2);
            const int c = col0 + n0w + nt * 8 + (lane & 3) * 2;
            float d0 = acc[mt][nt][0], d1 = acc[mt][nt][1];
            float d2 = acc[mt][nt][2], d3 = acc[mt][nt][3];
            if (EPI == 1) {
                d0 = softcap(d0); d1 = softcap(d1);
                d2 = softcap(d2); d3 = softcap(d3);
            }
            if (EPI <= 1) {
                *reinterpret_cast<float2*>(C + (long long)r * ldc + c)       = make_float2(d0, d1);
                *reinterpret_cast<float2*>(C + (long long)(r + 8) * ldc + c) = make_float2(d2, d3);
            } else {
                __nv_bfloat16 h0 = __float2bfloat16(d0), h1 = __float2bfloat16(d1);
                __nv_bfloat16 h2 = __float2bfloat16(d2), h3 = __float2bfloat16(d3);
                __nv_bfloat162 hv0(h0, h1), hv1(h2, h3);
                __nv_bfloat162 lv0(__float2bfloat16(d0 - __bfloat162float(h0)),
                                   __float2bfloat16(d1 - __bfloat162float(h1)));
                __nv_bfloat162 lv1(__float2bfloat16(d2 - __bfloat162float(h2)),
                                   __float2bfloat16(d3 - __bfloat162float(h3)));
                *reinterpret_cast<__nv_bfloat162*>(Ch + (long long)r * ldc + c)       = hv0;
                *reinterpret_cast<__nv_bfloat162*>(Cl + (long long)r * ldc + c)       = lv0;
                *reinterpret_cast<__nv_bfloat162*>(Ch + (long long)(r + 8) * ldc + c) = hv1;
                *reinterpret_cast<__nv_bfloat162*>(Cl + (long long)(r + 8) * ldc + c) = lv1;
            }
        }
    }
}

// ---------------------------------------------------------------------------
// Fused flash attention v2 (R13 core, + bbase param for half-launches).
// ---------------------------------------------------------------------------
#define FL_SLOT  65536
#define FL_PBASE (2 * FL_SLOT)           // 131072
#define FL_QBASE (FL_PBASE + 32768)      // 163840
#define FL_SMEM  (FL_QBASE + 65536 + 128)

__global__ void __launch_bounds__(256, 1)
flash_attn(const __nv_bfloat16* __restrict__ qh, const __nv_bfloat16* __restrict__ ql,
           const __nv_bfloat16* __restrict__ vh, const __nv_bfloat16* __restrict__ vl,
           __nv_bfloat16* __restrict__ ohh, __nv_bfloat16* __restrict__ oll, int bbase)
{
    extern __shared__ char dsm[];
    __shared__ float redm[64][4];
    __shared__ float redl[64][4];

    const int tid  = threadIdx.x;
    const int wid  = tid >> 5;
    const int lane = tid & 31;
    const int wm = wid >> 2;
    const int wn = wid & 3;
    const int b  = bbase - blockIdx.x;   // heavy q-blocks first within each half
    const int h  = blockIdx.y;
    const int kvh = h >> 1;
    const int qcol = h * HD;
    const int kcol = K_OFF + kvh * HD;
    const int vrow = kvh * HD;
    const int row0 = b * 64;
    const int jmax = b >> 1;

    const uint32_t raw = smem_u32(dsm);
    const uint32_t sb0 = (raw + 127) & ~127u;
    const uint32_t pB  = sb0 + FL_PBASE;
    const uint32_t qB  = sb0 + FL_QBASE;

    const int aRowL = lane & 15;
    const int aColL = (lane >> 4) << 3;
    const int bRowL = (lane & 7) + ((lane >> 4) << 3);
    const int bColL = ((lane >> 3) & 1) << 3;

    float o[2][8][4];
    #pragma unroll
    for (int mt = 0; mt < 2; mt++)
        #pragma unroll
        for (int nt = 0; nt < 8; nt++)
            #pragma unroll
            for (int e = 0; e < 4; e++) o[mt][nt][e] = 0.0f;
    float mrow[4] = {NEG_INF, NEG_INF, NEG_INF, NEG_INF};
    float lrow[4] = {0.0f, 0.0f, 0.0f, 0.0f};

    // ---- persistent Q load ----
    #pragma unroll
    for (int i = 0; i < 8; i++) {
        int idx = tid + i * 256;
        int r = idx >> 5, ch = idx & 31;
        int dblk = ch >> 3, c8 = ch & 7;
        uint32_t off = (uint32_t)(r * 128 + c8 * 16);
        off ^= (off >> 3) & 0x70;
        long long g = (long long)(row0 + r) * QKV_COLS + qcol + ch * 8;
        ldgsts16(qB + dblk * 8192 + off,         qh + g);
        ldgsts16(qB + 32768 + dblk * 8192 + off, ql + g);
    }
    asm volatile("cp.async.commit_group;" ::: "memory");

    auto issueK = [&](int j, int kc, int sl) {
        const uint32_t st = sb0 + sl * FL_SLOT;
        const int krow0 = j * 128;
        #pragma unroll
        for (int i = 0; i < 8; i++) {
            int idx = tid + i * 256;
            int r = idx >> 4, ch = idx & 15;
            int sub = ch >> 3, c8 = ch & 7;
            uint32_t off = (uint32_t)(r * 128 + c8 * 16);
            off ^= (off >> 3) & 0x70;
            long long g = (long long)(krow0 + r) * QKV_COLS + kcol + kc * 128 + ch * 8;
            ldgsts16(st + sub * 16384 + off,         qh + g);
            ldgsts16(st + 32768 + sub * 16384 + off, ql + g);
        }
    };
    auto issueV = [&](int j, int tc, int sl) {
        const uint32_t st = sb0 + sl * FL_SLOT;
        const int t0 = j * 128 + tc * 64;
        #pragma unroll
        for (int i = 0; i < 8; i++) {
            int idx = tid + i * 256;
            int r = idx >> 3, ch = idx & 7;
            uint32_t off = (uint32_t)(r * 128 + ch * 16);
            off ^= (off >> 3) & 0x70;
            long long g = (long long)(vrow + r) * T_SEQ + t0 + ch * 8;
            ldgsts16(st + off,         vh + g);
            ldgsts16(st + 32768 + off, vl + g);
        }
    };
    auto issueChunk = [&](int j, int c, int sl) {
        if (c < 2) issueK(j, c, sl); else issueV(j, c - 2, sl);
    };

    issueChunk(0, 0, 0);
    asm volatile("cp.async.commit_group;" ::: "memory");

    float sacc[2][4][4];
    int step = 0;
    #pragma unroll 1
    for (int j = 0; j <= jmax; j++) {
        #pragma unroll
        for (int mt = 0; mt < 2; mt++)
            #pragma unroll
            for (int nt = 0; nt < 4; nt++)
                #pragma unroll
                for (int e = 0; e < 4; e++) sacc[mt][nt][e] = 0.0f;

        #pragma unroll 1
        for (int c = 0; c < 4; c++) {
            int nj = j, nc = c + 1;
            if (nc == 4) { nj = j + 1; nc = 0; }
            if (nj <= jmax) issueChunk(nj, nc, (step + 1) & 1);
            asm volatile("cp.async.commit_group;" ::: "memory");
            asm volatile("cp.async.wait_group 1;" ::: "memory");
            __syncthreads();
            const uint32_t st = sb0 + (step & 1) * FL_SLOT;

            if (c < 2) {
                #pragma unroll
                for (int sub = 0; sub < 2; sub++) {
                    const uint32_t qHi = qB + (c * 2 + sub) * 8192;
                    const uint32_t qLo = qHi + 32768;
                    const uint32_t kHi = st + sub * 16384;
                    const uint32_t kLo = kHi + 32768;
                    #pragma unroll
                    for (int ks = 0; ks < 4; ks++) {
                        const int k0e = ks * 16;
                        uint32_t ah[2][4], al[2][4], bh[2][4], bl[2][4];
                        #pragma unroll
                        for (int mt = 0; mt < 2; mt++) {
                            uint32_t off = (uint32_t)((wm * 32 + mt * 16 + aRowL) * 128 + (k0e + aColL) * 2);
                            off ^= (off >> 3) & 0x70;
                            ldsm4(ah[mt], qHi + off);
                        }
                        #pragma unroll
                        for (int p = 0; p < 2; p++) {
                            uint32_t off = (uint32_t)((wn * 32 + p * 16 + bRowL) * 128 + (k0e + bColL) * 2);
                            off ^= (off >> 3) & 0x70;
                            ldsm4(bh[p], kHi + off);
                        }
                        #pragma unroll
                        for (int mt = 0; mt < 2; mt++)
                            #pragma unroll
                            for (int nt = 0; nt < 4; nt++)
                                mma16816(sacc[mt][nt], ah[mt], &bh[nt >> 1][(nt & 1) * 2]);
                        #pragma unroll
                        for (int p = 0; p < 2; p++) {
                            uint32_t off = (uint32_t)((wn * 32 + p * 16 + bRowL) * 128 + (k0e + bColL) * 2);
                            off ^= (off >> 3) & 0x70;
                            ldsm4(bl[p], kLo + off);
                        }
                        #pragma unroll
                        for (int mt = 0; mt < 2; mt++)
                            #pragma unroll
                            for (int nt = 0; nt < 4; nt++)
                                mma16816(sacc[mt][nt], ah[mt], &bl[nt >> 1][(nt & 1) * 2]);
                        #pragma unroll
                        for (int mt = 0; mt < 2; mt++) {
                            uint32_t off = (uint32_t)((wm * 32 + mt * 16 + aRowL) * 128 + (k0e + aColL) * 2);
                            off ^= (off >> 3) & 0x70;
                            ldsm4(al[mt], qLo + off);
                        }
                        #pragma unroll
                        for (int mt = 0; mt < 2; mt++)
                            #pragma unroll
                            for (int nt = 0; nt < 4; nt++)
                                mma16816(sacc[mt][nt], al[mt], &bh[nt >> 1][(nt & 1) * 2]);
                    }
                }

                if (c == 1) {
                    const bool diag = (j == jmax);
                    #pragma unroll
                    for (int mt = 0; mt < 2; mt++)
                        #pragma unroll
                        for (int nt = 0; nt < 4; nt++)
                            #pragma unroll
                            for (int e = 0; e < 4; e++) {
                                float x = softcap(sacc[mt][nt][e]);
                                if (diag) {
                                    int rg = row0 + wm * 32 + mt * 16 + (lane >> 2) + ((e >> 1) << 3);
                                    int cg = j * 128 + wn * 32 + nt * 8 + ((lane & 3) << 1) + (e & 1);
                                    if (cg > rg) x = NEG_INF;
                                }
                                sacc[mt][nt][e] = x;
                            }
                    float alpha[4];
                    #pragma unroll
                    for (int mt = 0; mt < 2; mt++)
                        #pragma unroll
                        for (int hb = 0; hb < 2; hb++) {
                            float mm = NEG_INF;
                            #pragma unroll
                            for (int nt = 0; nt < 4; nt++)
                                mm = fmaxf(mm, fmaxf(sacc[mt][nt][2 * hb], sacc[mt][nt][2 * hb + 1]));
                            mm = fmaxf(mm, __shfl_xor_sync(0xffffffffu, mm, 1));
                            mm = fmaxf(mm, __shfl_xor_sync(0xffffffffu, mm, 2));
                            if ((lane & 3) == 0)
                                redm[wm * 32 + mt * 16 + (lane >> 2) + hb * 8][wn] = mm;
                        }
                    __syncthreads();
                    #pragma unroll
                    for (int mt = 0; mt < 2; mt++)
                        #pragma unroll
                        for (int hb = 0; hb < 2; hb++) {
                            int r = wm * 32 + mt * 16 + (lane >> 2) + hb * 8;
                            int s = mt * 2 + hb;
                            float bm = fmaxf(fmaxf(redm[r][0], redm[r][1]),
                                             fmaxf(redm[r][2], redm[r][3]));
                            float mn = fmaxf(mrow[s], bm);
                            alpha[s] = __expf(mrow[s] - mn);
                            mrow[s] = mn;
                        }
                    float ps[4] = {0.0f, 0.0f, 0.0f, 0.0f};
                    #pragma unroll
                    for (int mt = 0; mt < 2; mt++)
                        #pragma unroll
                        for (int nt = 0; nt < 4; nt++)
                            #pragma unroll
                            for (int e = 0; e < 4; e++) {
                                int s = mt * 2 + (e >> 1);
                                float pe = __expf(sacc[mt][nt][e] - mrow[s]);
                                sacc[mt][nt][e] = pe;
                                ps[s] += pe;
                            }
                    #pragma unroll
                    for (int mt = 0; mt < 2; mt++)
                        #pragma unroll
                        for (int hb = 0; hb < 2; hb++) {
                            int s = mt * 2 + hb;
                            float v = ps[s];
                            v += __shfl_xor_sync(0xffffffffu, v, 1);
                            v += __shfl_xor_sync(0xffffffffu, v, 2);
                            if ((lane & 3) == 0)
                                redl[wm * 32 + mt * 16 + (lane >> 2) + hb * 8][wn] = v;
                        }
                    __syncthreads();
                    #pragma unroll
                    for (int mt = 0; mt < 2; mt++)
                        #pragma unroll
                        for (int hb = 0; hb < 2; hb++) {
                            int r = wm * 32 + mt * 16 + (lane >> 2) + hb * 8;
                            int s = mt * 2 + hb;
                            float bs = (redl[r][0] + redl[r][1]) + (redl[r][2] + redl[r][3]);
                            lrow[s] = lrow[s] * alpha[s] + bs;
                        }
                    #pragma unroll
                    for (int mt = 0; mt < 2; mt++)
                        #pragma unroll
                        for (int nt = 0; nt < 8; nt++)
                            #pragma unroll
                            for (int e = 0; e < 4; e++)
                                o[mt][nt][e] *= alpha[mt * 2 + (e >> 1)];
                    #pragma unroll
                    for (int mt = 0; mt < 2; mt++)
                        #pragma unroll
                        for (int nt = 0; nt < 4; nt++)
                            #pragma unroll
                            for (int hb = 0; hb < 2; hb++) {
                                int r = wm * 32 + mt * 16 + (lane >> 2) + hb * 8;
                                int col = wn * 32 + nt * 8 + ((lane & 3) << 1);
                                uint32_t hbase = pB + ((col >> 6) ? 8192u : 0u);
                                uint32_t off = (uint32_t)(r * 128 + (col & 63) * 2);
                                off ^= (off >> 3) & 0x70;
                                float p0 = sacc[mt][nt][2 * hb], p1 = sacc[mt][nt][2 * hb + 1];
                                __nv_bfloat16 h0 = __float2bfloat16(p0), h1 = __float2bfloat16(p1);
                                __nv_bfloat162 hv(h0, h1);
                                __nv_bfloat162 lv(__float2bfloat16(p0 - __bfloat162float(h0)),
                                                  __float2bfloat16(p1 - __bfloat162float(h1)));
                                sts32(hbase + off,         *reinterpret_cast<uint32_t*>(&hv));
                                sts32(hbase + 16384 + off, *reinterpret_cast<uint32_t*>(&lv));
                            }
                }
            } else {
                const int tc = c - 2;
                const uint32_t PhA = pB + tc * 8192;
                const uint32_t PlA = PhA + 16384;
                #pragma unroll
                for (int ks = 0; ks < 4; ks++) {
                    const int k0e = ks * 16;
                    uint32_t ap[2][4], apl[2][4], bvh[4][4], bvl[4][4];
                    #pragma unroll
                    for (int mt = 0; mt < 2; mt++) {
                        uint32_t off = (uint32_t)((wm * 32 + mt * 16 + aRowL) * 128 + (k0e + aColL) * 2);
                        off ^= (off >> 3) & 0x70;
                        ldsm4(ap[mt], PhA + off);
                    }
                    #pragma unroll
                    for (int p = 0; p < 4; p++) {
                        uint32_t off = (uint32_t)((wn * 64 + p * 16 + bRowL) * 128 + (k0e + bColL) * 2);
                        off ^= (off >> 3) & 0x70;
                        ldsm4(bvh[p], st + off);
                    }
                    #pragma unroll
                    for (int mt = 0; mt < 2; mt++)
                        #pragma unroll
                        for (int nt = 0; nt < 8; nt++)
                            mma16816(o[mt][nt], ap[mt], &bvh[nt >> 1][(nt & 1) * 2]);
                    #pragma unroll
                    for (int p = 0; p < 4; p++) {
                        uint32_t off = (uint32_t)((wn * 64 + p * 16 + bRowL) * 128 + (k0e + bColL) * 2);
                        off ^= (off >> 3) & 0x70;
                        ldsm4(bvl[p], st + 32768 + off);
                    }
                    #pragma unroll
                    for (int mt = 0; mt < 2; mt++)
                        #pragma unroll
                        for (int nt = 0; nt < 8; nt++)
                            mma16816(o[mt][nt], ap[mt], &bvl[nt >> 1][(nt & 1) * 2]);
                    #pragma unroll
                    for (int mt = 0; mt < 2; mt++) {
                        uint32_t off = (uint32_t)((wm * 32 + mt * 16 + aRowL) * 128 + (k0e + aColL) * 2);
                        off ^= (off >> 3) & 0x70;
                        ldsm4(apl[mt], PlA + off);
                    }
                    #pragma unroll
                    for (int mt = 0; mt < 2; mt++)
                        #pragma unroll
                        for (int nt = 0; nt < 8; nt++)
                            mma16816(o[mt][nt], apl[mt], &bvh[nt >> 1][(nt & 1) * 2]);
                }
            }
            __syncthreads();
            step++;
        }
    }

    float invl[4];
    #pragma unroll
    for (int s = 0; s < 4; s++) invl[s] = 1.0f / lrow[s];

    #pragma unroll
    for (int mt = 0; mt < 2; mt++) {
        #pragma unroll
        for (int nt = 0; nt < 8; nt++) {
            const int r = row0 + wm * 32 + mt * 16 + (lane >> 2);
            const int col = qcol + wn * 64 + nt * 8 + ((lane & 3) << 1);
            float d0 = o[mt][nt][0] * invl[mt * 2];
            float d1 = o[mt][nt][1] * invl[mt * 2];
            float d2 = o[mt][nt][2] * invl[mt * 2 + 1];
            float d3 = o[mt][nt][3] * invl[mt * 2 + 1];
            __nv_bfloat16 h0 = __float2bfloat16(d0), h1 = __float2bfloat16(d1);
            __nv_bfloat16 h2 = __float2bfloat16(d2), h3 = __float2bfloat16(d3);
            __nv_bfloat162 hv0(h0, h1), hv1(h2, h3);
            __nv_bfloat162 lv0(__float2bfloat16(d0 - __bfloat162float(h0)),
                               __float2bfloat16(d1 - __bfloat162float(h1)));
            __nv_bfloat162 lv1(__float2bfloat16(d2 - __bfloat162float(h2)),
                               __float2bfloat16(d3 - __bfloat162float(h3)));
            *reinterpret_cast<__nv_bfloat162*>(ohh + (long long)r * ATTN_COLS + col)       = hv0;
            *reinterpret_cast<__nv_bfloat162*>(oll + (long long)r * ATTN_COLS + col)       = lv0;
            *reinterpret_cast<__nv_bfloat162*>(ohh + (long long)(r + 8) * ATTN_COLS + col) = hv1;
            *reinterpret_cast<__nv_bfloat162*>(oll + (long long)(r + 8) * ATTN_COLS + col) = lv1;
        }
    }
}

// ---------------------------------------------------------------------------
// fp32 -> (hi, lo) bf16 split, elementwise
// ---------------------------------------------------------------------------
__global__ void __launch_bounds__(256)
convsplit(const float4* __restrict__ x, __nv_bfloat162* __restrict__ hi,
          __nv_bfloat162* __restrict__ lo, long long n4)
{
    long long i = (long long)blockIdx.x * 256 + threadIdx.x;
    if (i >= n4) return;
    float4 v = x[i];
    __nv_bfloat16 h0 = __float2bfloat16(v.x), h1 = __float2bfloat16(v.y);
    __nv_bfloat16 h2 = __float2bfloat16(v.z), h3 = __float2bfloat16(v.w);
    hi[2 * i]     = __nv_bfloat162(h0, h1);
    hi[2 * i + 1] = __nv_bfloat162(h2, h3);
    lo[2 * i]     = __nv_bfloat162(__float2bfloat16(v.x - __bfloat162float(h0)),
                                   __float2bfloat16(v.y - __bfloat162float(h1)));
    lo[2 * i + 1] = __nv_bfloat162(__float2bfloat16(v.z - __bfloat162float(h2)),
                                   __float2bfloat16(v.w - __bfloat162float(h3)));
}

// ---------------------------------------------------------------------------
// Transpose + split: in[R,C] fp32 (ldin) -> out[C,R] (hi, lo) bf16 (ldout)
// ---------------------------------------------------------------------------
__global__ void __launch_bounds__(256)
tsplit(const float* __restrict__ in, int ldin, __nv_bfloat16* __restrict__ oh,
       __nv_bfloat16* __restrict__ ol, int ldout)
{
    __shared__ float t[32][33];
    int bx = blockIdx.x * 32, by = blockIdx.y * 32;
    int tx = threadIdx.x, ty = threadIdx.y;
    #pragma unroll
    for (int j = ty; j < 32; j += 8)
        t[j][tx] = in[(long long)(by + j) * ldin + bx + tx];
    __syncthreads();
    #pragma unroll
    for (int j = ty; j < 32; j += 8) {
        float v = t[tx][j];
        __nv_bfloat16 h = __float2bfloat16(v);
        long long o = (long long)(bx + j) * ldout + by + tx;
        oh[o] = h;
        ol[o] = __float2bfloat16(v - __bfloat162float(h));
    }
}

// ---------------------------------------------------------------------------
// Fused RoPE + split: reads fp32 qkv (Q,K region), writes split bf16 pair
// ---------------------------------------------------------------------------
__global__ void __launch_bounds__(256)
rope_split(const float* __restrict__ qkv, const int* __restrict__ positions,
           __nv_bfloat16* __restrict__ oh, __nv_bfloat16* __restrict__ ol)
{
    int idx = blockIdx.x * blockDim.x + threadIdx.x;
    int i = idx & 127;
    int h = (idx >> 7) % (NH + NKV);
    int t = idx / (128 * (NH + NKV));
    if (t >= T_SEQ) return;
    float pos = (float)positions[t];
    float inv = powf(10000.0f, -((2.0f * (float)i) / (float)HD));
    float f = pos * inv;
    float c, s;
    sincosf(f, &s, &c);
    long long base = (long long)t * QKV_COLS + h * HD;
    float x1 = qkv[base + i], x2 = qkv[base + i + HD / 2];
    float y1 = x1 * c - x2 * s;
    float y2 = x2 * c + x1 * s;
    __nv_bfloat16 h1 = __float2bfloat16(y1);
    __nv_bfloat16 h2 = __float2bfloat16(y2);
    oh[base + i]          = h1;
    ol[base + i]          = __float2bfloat16(y1 - __bfloat162float(h1));
    oh[base + i + HD / 2] = h2;
    ol[base + i + HD / 2] = __float2bfloat16(y2 - __bfloat162float(h2));
}

// ---------------------------------------------------------------------------
// kernel_launch — graph-capturable, allocation-free.
// Two-stream pipeline:
//   s0: tsplit(w_qkv) | QKV | rope | tsplitV | flashH(b16-31) | OprojB(rows 1024+)
//   s1: convsplit(hidden), tsplit(w_o) | flashL(b0-15) | OprojA(rows 0-1023)
// ---------------------------------------------------------------------------
extern "C" void kernel_launch(void* const* d_in, const int* in_sizes, int n_in,
                              void* d_out, int out_size)
{
    const int*   positions = (const int*)  d_in[0];
    const float* hidden    = (const float*)d_in[1];
    const float* w_qkv     = (const float*)d_in[2];
    const float* w_o       = (const float*)d_in[3];
    float*       out       = (float*)d_out;

    float *qkv;
    __nv_bfloat16 *hch, *hcl, *wqh, *wql, *woh, *wol, *qch, *qcl, *vch, *vcl, *ach, *acl;
    cudaGetSymbolAddress((void**)&qkv, g_qkv);
    cudaGetSymbolAddress((void**)&hch, g_hc_h);    cudaGetSymbolAddress((void**)&hcl, g_hc_l);
    cudaGetSymbolAddress((void**)&wqh, g_wqkvT_h); cudaGetSymbolAddress((void**)&wql, g_wqkvT_l);
    cudaGetSymbolAddress((void**)&woh, g_woT_h);   cudaGetSymbolAddress((void**)&wol, g_woT_l);
    cudaGetSymbolAddress((void**)&qch, g_qkvc_h);  cudaGetSymbolAddress((void**)&qcl, g_qkvc_l);
    cudaGetSymbolAddress((void**)&vch, g_vTc_h);   cudaGetSymbolAddress((void**)&vcl, g_vTc_l);
    cudaGetSymbolAddress((void**)&ach, g_attnc_h); cudaGetSymbolAddress((void**)&acl, g_attnc_l);

    cudaFuncSetAttribute(gemm_mma<0, 0>, cudaFuncAttributeMaxDynamicSharedMemorySize, GEMM_SMEM);
    cudaFuncSetAttribute(flash_attn, cudaFuncAttributeMaxDynamicSharedMemorySize, FL_SMEM);

    cudaStream_t s1;
    cudaStreamCreateWithFlags(&s1, cudaStreamNonBlocking);
    cudaEvent_t eFork, eHid, eWo, eKV, eA;
    cudaEventCreateWithFlags(&eFork, cudaEventDisableTiming);
    cudaEventCreateWithFlags(&eHid,  cudaEventDisableTiming);
    cudaEventCreateWithFlags(&eWo,   cudaEventDisableTiming);
    cudaEventCreateWithFlags(&eKV,   cudaEventDisableTiming);
    cudaEventCreateWithFlags(&eA,    cudaEventDisableTiming);

    // Fork s1
    cudaEventRecord(eFork, 0);
    cudaStreamWaitEvent(s1, eFork, 0);

    // s1: hidden split (needed by QKV), then w_o transpose (needed by O-proj)
    {
        long long n4 = (long long)T_SEQ * HID / 4;
        convsplit<<<(unsigned)((n4 + 255) / 256), 256, 0, s1>>>((const float4*)hidden,
            (__nv_bfloat162*)hch, (__nv_bfloat162*)hcl, n4);
    }
    cudaEventRecord(eHid, s1);
    tsplit<<<dim3(HID / 32, ATTN_COLS / 32), dim3(32, 8), 0, s1>>>(w_o, HID, woh, wol, ATTN_COLS);
    cudaEventRecord(eWo, s1);

    // s0: w_qkv transpose, then QKV projection
    tsplit<<<dim3(QKV_COLS / 32, HID / 32), dim3(32, 8)>>>(w_qkv, QKV_COLS, wqh, wql, HID);
    cudaStreamWaitEvent(0, eHid, 0);

    gemm_mma<0, 0><<<dim3(QKV_COLS / 128, T_SEQ / 128, 1), 256, GEMM_SMEM>>>(
        hch, hcl, wqh, wql, qkv, nullptr, nullptr,
        HID, HID, HID, QKV_COLS, 0, 0, 0, 1);

    // s0: RoPE + V transpose
    rope_split<<<(T_SEQ * (NH + NKV) * (HD / 2)) / 256, 256>>>(qkv, positions, qch, qcl);
    tsplit<<<dim3((NKV * HD) / 32, T_SEQ / 32), dim3(32, 8)>>>(qkv + V_OFF, QKV_COLS, vch, vcl, T_SEQ);
    cudaEventRecord(eKV, 0);

    // s0: heavy flash half (q-blocks 16-31 -> rows 1024-2047)
    flash_attn<<<dim3(16, NH), 256, FL_SMEM>>>(qch, qcl, vch, vcl, ach, acl, 31);

    // s1: light flash half (q-blocks 0-15 -> rows 0-1023), then its O-proj
    cudaStreamWaitEvent(s1, eKV, 0);
    flash_attn<<<dim3(16, NH), 256, FL_SMEM, s1>>>(qch, qcl, vch, vcl, ach, acl, 15);
    gemm_mma<0, 0><<<dim3(HID / 128, 8, 1), 256, GEMM_SMEM, s1>>>(
        ach, acl, woh, wol, out, nullptr, nullptr,
        ATTN_COLS, ATTN_COLS, ATTN_COLS, HID, 0, 0, 0, 1);
    cudaEventRecord(eA, s1);

    // s0: O-proj for rows 1024-2047 (needs w_o prep + flashH)
    cudaStreamWaitEvent(0, eWo, 0);
    gemm_mma<0, 0><<<dim3(HID / 128, 8, 1), 256, GEMM_SMEM>>>(
        ach + (long long)1024 * ATTN_COLS, acl + (long long)1024 * ATTN_COLS, woh, wol,
        out + (long long)1024 * HID, nullptr, nullptr,
        ATTN_COLS, ATTN_COLS, ATTN_COLS, HID, 0, 0, 0, 1);

    // join s1 into s0
    cudaStreamWaitEvent(0, eA, 0);
}